// round 6
// baseline (speedup 1.0000x reference)
#include <cuda_runtime.h>
#include <cuda_bf16.h>
#include <cuda_fp16.h>

#define N_NODES 50000
#define N_EDGES 800000
#define IN_F 256
#define HFD 128   // HEADS * OUT_FEATS
#define NHEAD 4
#define SCAN_B 196   // ceil(50000/256)
#define GEMM_B 391   // ceil(50000/128)
#define HIST_B 391
#define FUSED_B (GEMM_B + HIST_B)

// -------- scratch (device globals; no allocation allowed) --------
__device__ __half g_feat_h16[N_NODES * HFD]; // projected features, fp16 (agg-only consumer)
__device__ float g_el[N_NODES * NHEAD];      // attn_l dot  [N,4]
__device__ float g_er[N_NODES * NHEAD];      // attn_r dot  [N,4]
__device__ int   g_deg[N_NODES];             // per-dst degree (zero-init .bss; re-zeroed by scanC)
__device__ int   g_rowptr[N_NODES + 1];      // CSR row pointers
__device__ int   g_cursor[N_NODES];          // scatter cursors
__device__ int   g_poff[SCAN_B];             // scan partials
__device__ int2  g_edge[N_EDGES];            // (src, bits(weight)) sorted by dst

__device__ __forceinline__ unsigned f2tf32(float f) {
    unsigned u;
    asm("cvt.rna.tf32.f32 %0, %1;" : "=r"(u) : "f"(f));
    return u;
}

// =================================================================
// Kernel 1 (fused): blocks [0,GEMM_B): tf32 GEMM feat @ W_fc^T with
//   el/er computed in the epilogue; feat_hf stored fp16.
// blocks [GEMM_B, FUSED_B): dst-degree histogram (runs concurrently).
// =================================================================
__global__ __launch_bounds__(256) void k_gemm_hist(const float* __restrict__ feat,
                                                   const float* __restrict__ Wfc,
                                                   const float* __restrict__ attn_l,
                                                   const float* __restrict__ attn_r,
                                                   const int* __restrict__ dst) {
    const int tid = threadIdx.x;

    if (blockIdx.x >= GEMM_B) {
        int b = blockIdx.x - GEMM_B;
        for (int e = b * 256 + tid; e < N_EDGES; e += HIST_B * 256)
            atomicAdd(&g_deg[__ldg(&dst[e])], 1);
        return;
    }

    __shared__ unsigned As[32][132];   // [k][m], tf32 bits, padded
    __shared__ unsigned Bs[32][132];   // [k][n], tf32 bits, padded

    const int lane = tid & 31;
    const int wid = tid >> 5;
    const int warp_m = wid >> 2;       // 0..1
    const int warp_n = wid & 3;        // 0..3  (== head index h)
    const int row0 = blockIdx.x * 128;

    float acc[4][4][4];                // [mtile][ntile][frag]
#pragma unroll
    for (int i = 0; i < 4; i++)
#pragma unroll
        for (int j = 0; j < 4; j++)
#pragma unroll
            for (int q = 0; q < 4; q++) acc[i][j][q] = 0.f;

    const int gq = lane >> 2;          // group id 0..7 (row within 8)
    const int tg = lane & 3;           // thread-in-group 0..3 (col pair)

    for (int chunk = 0; chunk < 8; chunk++) {
        const int kglob = chunk * 32;
#pragma unroll
        for (int i = 0; i < 4; i++) {
            int idx = tid + i * 256;
            int m = idx & 127;
            int k4 = (idx >> 7) * 4;
            int row = row0 + m;
            if (row >= N_NODES) row = N_NODES - 1;
            float4 v = *(const float4*)(feat + (size_t)row * IN_F + kglob + k4);
            As[k4 + 0][m] = f2tf32(v.x);
            As[k4 + 1][m] = f2tf32(v.y);
            As[k4 + 2][m] = f2tf32(v.z);
            As[k4 + 3][m] = f2tf32(v.w);
        }
#pragma unroll
        for (int i = 0; i < 4; i++) {
            int idx = tid + i * 256;
            int n = idx & 127;
            int k4 = (idx >> 7) * 4;
            float4 v = *(const float4*)(Wfc + (size_t)n * IN_F + kglob + k4);
            Bs[k4 + 0][n] = f2tf32(v.x);
            Bs[k4 + 1][n] = f2tf32(v.y);
            Bs[k4 + 2][n] = f2tf32(v.z);
            Bs[k4 + 3][n] = f2tf32(v.w);
        }
        __syncthreads();

#pragma unroll
        for (int kk = 0; kk < 4; kk++) {
            const int kb = kk * 8;
            unsigned a[4][4], b[4][2];
#pragma unroll
            for (int mt = 0; mt < 4; mt++) {
                int rs = warp_m * 64 + mt * 16;
                a[mt][0] = As[kb + tg][rs + gq];
                a[mt][1] = As[kb + tg][rs + gq + 8];
                a[mt][2] = As[kb + tg + 4][rs + gq];
                a[mt][3] = As[kb + tg + 4][rs + gq + 8];
            }
#pragma unroll
            for (int nt = 0; nt < 4; nt++) {
                int ns = warp_n * 32 + nt * 8;
                b[nt][0] = Bs[kb + tg][ns + gq];
                b[nt][1] = Bs[kb + tg + 4][ns + gq];
            }
#pragma unroll
            for (int mt = 0; mt < 4; mt++)
#pragma unroll
                for (int nt = 0; nt < 4; nt++) {
                    asm volatile(
                        "mma.sync.aligned.m16n8k8.row.col.f32.tf32.tf32.f32 "
                        "{%0,%1,%2,%3}, {%4,%5,%6,%7}, {%8,%9}, {%0,%1,%2,%3};"
                        : "+f"(acc[mt][nt][0]), "+f"(acc[mt][nt][1]),
                          "+f"(acc[mt][nt][2]), "+f"(acc[mt][nt][3])
                        : "r"(a[mt][0]), "r"(a[mt][1]), "r"(a[mt][2]), "r"(a[mt][3]),
                          "r"(b[nt][0]), "r"(b[nt][1]));
                }
        }
        __syncthreads();
    }

    // attn vectors for this warp's 8 columns (head = warp_n)
    float al_v[8], ar_v[8];
#pragma unroll
    for (int nt = 0; nt < 4; nt++) {
        int col = warp_n * 32 + nt * 8 + tg * 2;
        al_v[nt * 2 + 0] = __ldg(&attn_l[col]);
        al_v[nt * 2 + 1] = __ldg(&attn_l[col + 1]);
        ar_v[nt * 2 + 0] = __ldg(&attn_r[col]);
        ar_v[nt * 2 + 1] = __ldg(&attn_r[col + 1]);
    }

    // epilogue: store fp16 feat_hf + compute el/er from accumulators
#pragma unroll
    for (int mt = 0; mt < 4; mt++) {
        float pl0 = 0.f, pl1 = 0.f, pr0 = 0.f, pr1 = 0.f;
#pragma unroll
        for (int nt = 0; nt < 4; nt++) {
            int col = warp_n * 32 + nt * 8 + tg * 2;
            int r0 = row0 + warp_m * 64 + mt * 16 + gq;
            if (r0 < N_NODES) {
                __half2 v = __floats2half2_rn(acc[mt][nt][0], acc[mt][nt][1]);
                *(__half2*)&g_feat_h16[(size_t)r0 * HFD + col] = v;
            }
            int r1 = r0 + 8;
            if (r1 < N_NODES) {
                __half2 v = __floats2half2_rn(acc[mt][nt][2], acc[mt][nt][3]);
                *(__half2*)&g_feat_h16[(size_t)r1 * HFD + col] = v;
            }
            pl0 += acc[mt][nt][0] * al_v[nt * 2] + acc[mt][nt][1] * al_v[nt * 2 + 1];
            pl1 += acc[mt][nt][2] * al_v[nt * 2] + acc[mt][nt][3] * al_v[nt * 2 + 1];
            pr0 += acc[mt][nt][0] * ar_v[nt * 2] + acc[mt][nt][1] * ar_v[nt * 2 + 1];
            pr1 += acc[mt][nt][2] * ar_v[nt * 2] + acc[mt][nt][3] * ar_v[nt * 2 + 1];
        }
#pragma unroll
        for (int o = 1; o < 4; o <<= 1) {
            pl0 += __shfl_xor_sync(0xffffffffu, pl0, o);
            pl1 += __shfl_xor_sync(0xffffffffu, pl1, o);
            pr0 += __shfl_xor_sync(0xffffffffu, pr0, o);
            pr1 += __shfl_xor_sync(0xffffffffu, pr1, o);
        }
        if (tg == 0) {
            int r0 = row0 + warp_m * 64 + mt * 16 + gq;
            if (r0 < N_NODES) {
                g_el[r0 * NHEAD + warp_n] = pl0;
                g_er[r0 * NHEAD + warp_n] = pr0;
            }
            int r1 = r0 + 8;
            if (r1 < N_NODES) {
                g_el[r1 * NHEAD + warp_n] = pl1;
                g_er[r1 * NHEAD + warp_n] = pr1;
            }
        }
    }
}

// ---------- block-wide exclusive scan helper (256 threads) ----------
__device__ __forceinline__ int block_excl_scan_256(int v) {
    int lane = threadIdx.x & 31, wid = threadIdx.x >> 5;
    int incl = v;
#pragma unroll
    for (int o = 1; o < 32; o <<= 1) {
        int n = __shfl_up_sync(0xffffffffu, incl, o);
        if (lane >= o) incl += n;
    }
    __shared__ int wsum[8];
    if (lane == 31) wsum[wid] = incl;
    __syncthreads();
    int woff = 0;
    if (wid == 0 && lane < 8) {
        int wv = wsum[lane];
        int acc = wv;
#pragma unroll
        for (int o = 1; o < 8; o <<= 1) {
            int n = __shfl_up_sync(0xffu, acc, o);
            if (lane >= o) acc += n;
        }
        wsum[lane] = acc - wv;   // exclusive warp offsets
    }
    __syncthreads();
    woff = wsum[wid];
    return incl - v + woff;
}

// =================================================================
// 3-phase exclusive scan -> rowptr, cursor.  scanC re-zeroes g_deg.
// =================================================================
__global__ __launch_bounds__(256) void k_scanA() {
    int idx = blockIdx.x * 256 + threadIdx.x;
    int v = (idx < N_NODES) ? g_deg[idx] : 0;
    int excl = block_excl_scan_256(v);
    if (threadIdx.x == 255) g_poff[blockIdx.x] = excl + v;
}

__global__ __launch_bounds__(256) void k_scanB() {
    int t = threadIdx.x;
    int v = (t < SCAN_B) ? g_poff[t] : 0;
    int excl = block_excl_scan_256(v);
    if (t < SCAN_B) g_poff[t] = excl;
}

__global__ __launch_bounds__(256) void k_scanC() {
    int idx = blockIdx.x * 256 + threadIdx.x;
    int v = (idx < N_NODES) ? g_deg[idx] : 0;
    int excl = block_excl_scan_256(v) + g_poff[blockIdx.x];
    if (idx < N_NODES) {
        g_rowptr[idx] = excl;
        g_cursor[idx] = excl;
        g_deg[idx] = 0;                       // self-clean for next replay
        if (idx == N_NODES - 1) g_rowptr[N_NODES] = excl + v;
    }
}

// =================================================================
// scatter edges into CSR order (by dst)
// =================================================================
__global__ __launch_bounds__(256) void k_scatter(const int* __restrict__ src,
                                                 const int* __restrict__ dst,
                                                 const float* __restrict__ ew) {
    int e = blockIdx.x * blockDim.x + threadIdx.x;
    if (e >= N_EDGES) return;
    int d = dst[e];
    int pos = atomicAdd(&g_cursor[d], 1);
    g_edge[pos] = make_int2(src[e], __float_as_int(ew[e]));
}

// ---------- per-edge body for k_agg ----------
__device__ __forceinline__ void agg_edge(uint2 raw, float el, float er_h, float w,
                                         const float4& We,
                                         float4& num, float4& den) {
    __half2 h01 = *reinterpret_cast<__half2*>(&raw.x);
    __half2 h23 = *reinterpret_cast<__half2*>(&raw.y);
    float2 f01 = __half22float2(h01);
    float2 f23 = __half22float2(h23);
    float c = el + er_h;
    float v0 = c + w * We.x;  v0 = fmaxf(v0, 0.2f * v0);
    float v1 = c + w * We.y;  v1 = fmaxf(v1, 0.2f * v1);
    float v2 = c + w * We.z;  v2 = fmaxf(v2, 0.2f * v2);
    float v3 = c + w * We.w;  v3 = fmaxf(v3, 0.2f * v3);
    float e0 = __expf(v0), e1 = __expf(v1), e2 = __expf(v2), e3 = __expf(v3);
    den.x += e0; den.y += e1; den.z += e2; den.w += e3;
    num.x = fmaf(e0, f01.x, num.x);
    num.y = fmaf(e1, f01.y, num.y);
    num.z = fmaf(e2, f23.x, num.z);
    num.w = fmaf(e3, f23.y, num.w);
}

// =================================================================
// aggregation. One warp per dst node; 4-edge unrolled, fp16 gathers.
// =================================================================
__global__ __launch_bounds__(256) void k_agg(float* __restrict__ out,
                                             const float* __restrict__ Wedge,
                                             const float* __restrict__ bias) {
    int d = (blockIdx.x * blockDim.x + threadIdx.x) >> 5;
    if (d >= N_NODES) return;
    int lane = threadIdx.x & 31;
    int h = lane >> 3;

    float4 We = *(const float4*)&Wedge[lane * 4];
    float4 b4 = *(const float4*)&bias[lane * 4];

    int beg = g_rowptr[d];
    int end = g_rowptr[d + 1];
    float er_h = g_er[d * NHEAD + h];

    float4 num = make_float4(0.f, 0.f, 0.f, 0.f);
    float4 den = make_float4(0.f, 0.f, 0.f, 0.f);

    for (int base = beg; base < end; base += 32) {
        int m = end - base;
        if (m > 32) m = 32;
        int2 sw = make_int2(0, 0);
        if (lane < m) sw = g_edge[base + lane];

        int j = 0;
        for (; j + 4 <= m; j += 4) {
            int   s0 = __shfl_sync(0xffffffffu, sw.x, j);
            int   s1 = __shfl_sync(0xffffffffu, sw.x, j + 1);
            int   s2 = __shfl_sync(0xffffffffu, sw.x, j + 2);
            int   s3 = __shfl_sync(0xffffffffu, sw.x, j + 3);
            float w0 = __int_as_float(__shfl_sync(0xffffffffu, sw.y, j));
            float w1 = __int_as_float(__shfl_sync(0xffffffffu, sw.y, j + 1));
            float w2 = __int_as_float(__shfl_sync(0xffffffffu, sw.y, j + 2));
            float w3 = __int_as_float(__shfl_sync(0xffffffffu, sw.y, j + 3));
            // all loads up front (MLP)
            uint2 r0 = *(const uint2*)&g_feat_h16[(size_t)s0 * HFD + lane * 4];
            uint2 r1 = *(const uint2*)&g_feat_h16[(size_t)s1 * HFD + lane * 4];
            uint2 r2 = *(const uint2*)&g_feat_h16[(size_t)s2 * HFD + lane * 4];
            uint2 r3 = *(const uint2*)&g_feat_h16[(size_t)s3 * HFD + lane * 4];
            float el0 = __ldg(&g_el[s0 * NHEAD + h]);
            float el1 = __ldg(&g_el[s1 * NHEAD + h]);
            float el2 = __ldg(&g_el[s2 * NHEAD + h]);
            float el3 = __ldg(&g_el[s3 * NHEAD + h]);

            agg_edge(r0, el0, er_h, w0, We, num, den);
            agg_edge(r1, el1, er_h, w1, We, num, den);
            agg_edge(r2, el2, er_h, w2, We, num, den);
            agg_edge(r3, el3, er_h, w3, We, num, den);
        }
        for (; j < m; j++) {
            int   s = __shfl_sync(0xffffffffu, sw.x, j);
            float w = __int_as_float(__shfl_sync(0xffffffffu, sw.y, j));
            uint2 r = *(const uint2*)&g_feat_h16[(size_t)s * HFD + lane * 4];
            float el = __ldg(&g_el[s * NHEAD + h]);
            agg_edge(r, el, er_h, w, We, num, den);
        }
    }

    float4 o;
    if (end > beg) {
        o.x = num.x / den.x + b4.x;
        o.y = num.y / den.y + b4.y;
        o.z = num.z / den.z + b4.z;
        o.w = num.w / den.w + b4.w;
    } else {
        o = b4;   // isolated node: just bias
    }
    *(float4*)&out[(size_t)d * HFD + lane * 4] = o;
}

// =================================================================
extern "C" void kernel_launch(void* const* d_in, const int* in_sizes, int n_in,
                              void* d_out, int out_size) {
    const float* feat   = (const float*)d_in[0];
    const float* ew     = (const float*)d_in[1];
    const int*   src    = (const int*)d_in[2];
    const int*   dst    = (const int*)d_in[3];
    const float* Wfc    = (const float*)d_in[4];
    const float* Wedge  = (const float*)d_in[5];
    const float* attn_l = (const float*)d_in[6];
    const float* attn_r = (const float*)d_in[7];
    const float* bias   = (const float*)d_in[8];
    float* out = (float*)d_out;

    (void)in_sizes; (void)n_in; (void)out_size;

    k_gemm_hist<<<FUSED_B, 256>>>(feat, Wfc, attn_l, attn_r, dst);
    k_scanA<<<SCAN_B, 256>>>();
    k_scanB<<<1, 256>>>();
    k_scanC<<<SCAN_B, 256>>>();
    k_scatter<<<(N_EDGES + 255) / 256, 256>>>(src, dst, ew);
    k_agg<<<(N_NODES * 32 + 255) / 256, 256>>>(out, Wedge, bias);
}